// round 5
// baseline (speedup 1.0000x reference)
#include <cuda_runtime.h>
#include <cstdint>
#include <cstddef>

// ===================== problem constants =====================
constexpr int C    = 128;            // channels
constexpr int NET  = 7;              // edge types
constexpr int KTOT = NET * C;        // 896
constexpr int NMAX = 100000;
constexpr int NSEGMAX = NMAX * NET;  // 700000
constexpr int EMAX = 700000;

// ===================== device scratch ========================
__device__ float    g_y[(size_t)NMAX * KTOT];   // 358.4 MB: y = x @ W (per-type blocks)
__device__ unsigned g_cnt[NSEGMAX];             // segment counts
__device__ unsigned g_off[NSEGMAX + 1];         // CSR offsets
__device__ unsigned g_cur[NSEGMAX];             // fill cursors
__device__ int      g_elist[EMAX];              // col index per CSR slot
__device__ unsigned g_bsum[1024];               // scan block sums
__device__ float    g_stats[2 * C];
__device__ float    g_scale[C];
__device__ float    g_shift[C];

// ===================== helpers ===============================
__device__ __forceinline__ uint32_t tf32_rna(float f) {
    uint32_t r;
    asm("cvt.rna.tf32.f32 %0, %1;" : "=r"(r) : "f"(f));
    return r;
}
__device__ __forceinline__ void mma_tf32(float* d, const uint32_t* a, uint32_t b0, uint32_t b1) {
    asm volatile(
        "mma.sync.aligned.m16n8k8.row.col.f32.tf32.tf32.f32 "
        "{%0,%1,%2,%3}, {%4,%5,%6,%7}, {%8,%9}, {%0,%1,%2,%3};"
        : "+f"(d[0]), "+f"(d[1]), "+f"(d[2]), "+f"(d[3])
        : "r"(a[0]), "r"(a[1]), "r"(a[2]), "r"(a[3]), "r"(b0), "r"(b1));
}

// block-wide inclusive scan (blockDim.x = 1024)
__device__ unsigned block_incl_scan(unsigned v, unsigned* wsum) {
    int lane = threadIdx.x & 31, wid = threadIdx.x >> 5;
#pragma unroll
    for (int d = 1; d < 32; d <<= 1) {
        unsigned n = __shfl_up_sync(0xffffffff, v, d);
        if (lane >= d) v += n;
    }
    if (lane == 31) wsum[wid] = v;
    __syncthreads();
    if (wid == 0) {
        unsigned w = wsum[lane];
#pragma unroll
        for (int d = 1; d < 32; d <<= 1) {
            unsigned n = __shfl_up_sync(0xffffffff, w, d);
            if (lane >= d) w += n;
        }
        wsum[lane] = w;
    }
    __syncthreads();
    return v + (wid > 0 ? wsum[wid - 1] : 0u);
}

// ===================== kernels ===============================

// K0: zero counts + stats
__global__ void zero_kernel(int nseg) {
    int i = blockIdx.x * blockDim.x + threadIdx.x;
    int stride = gridDim.x * blockDim.x;
    for (int j = i; j < nseg; j += stride) g_cnt[j] = 0u;
    if (i < 2 * C) g_stats[i] = 0.f;
}

// K1: count edges per (row, type), skipping self-slot type 6
__global__ void count_kernel(const int* __restrict__ row,
                             const int* __restrict__ et, int E) {
    int e = blockIdx.x * blockDim.x + threadIdx.x;
    if (e >= E) return;
    int t = et[e];
    if (t == NET - 1) return;
    atomicAdd(&g_cnt[row[e] * NET + t], 1u);
}

// K2a/b/c: exclusive scan of g_cnt -> g_off (+ cursors)
__global__ void __launch_bounds__(1024) scan1_kernel(int nseg) {
    __shared__ unsigned wsum[32];
    int i = blockIdx.x * 1024 + threadIdx.x;
    unsigned v = (i < nseg) ? g_cnt[i] : 0u;
    unsigned incl = block_incl_scan(v, wsum);
    if (i < nseg) g_off[i] = incl - v;
    if (threadIdx.x == 1023) g_bsum[blockIdx.x] = incl;
}
__global__ void __launch_bounds__(1024) scan2_kernel(int nblocks, int nseg) {
    __shared__ unsigned wsum[32];
    int t = threadIdx.x;
    unsigned v = (t < nblocks) ? g_bsum[t] : 0u;
    unsigned incl = block_incl_scan(v, wsum);
    if (t < nblocks) g_bsum[t] = incl - v;
    if (t == nblocks - 1) g_off[nseg] = incl;   // grand total
}
__global__ void __launch_bounds__(1024) scan3_kernel(int nseg) {
    int i = blockIdx.x * 1024 + threadIdx.x;
    if (i >= nseg) return;
    unsigned o = g_off[i] + g_bsum[blockIdx.x];
    g_off[i] = o;
    g_cur[i] = o;
}

// K3: fill CSR edge list
__global__ void fill_kernel(const int* __restrict__ row,
                            const int* __restrict__ col,
                            const int* __restrict__ et, int E) {
    int e = blockIdx.x * blockDim.x + threadIdx.x;
    if (e >= E) return;
    int t = et[e];
    if (t == NET - 1) return;
    int seg = row[e] * NET + t;
    unsigned pos = atomicAdd(&g_cur[seg], 1u);
    g_elist[pos] = col[e];
}

// K4: y = x @ W  via tf32 mma.sync.  CTA tile 256x128, 8 warps of 64x64.
constexpr int AS_STRIDE = 132;
constexpr int BS_STRIDE = 136;
constexpr int BM = 256;
constexpr int SMEM_A_FLOATS = BM * AS_STRIDE;          // 33792
constexpr int SMEM_B_FLOATS = 128 * BS_STRIDE;         // 17408
constexpr size_t GEMM_SMEM = (size_t)(SMEM_A_FLOATS + SMEM_B_FLOATS) * 4;  // 204800 B

__global__ void __launch_bounds__(256, 1)
gemm_kernel(const float* __restrict__ x, const float* __restrict__ w, int nrows) {
    extern __shared__ float sm[];
    float* As = sm;                       // [256][132] tf32 bits
    float* Bs = sm + SMEM_A_FLOATS;       // [128][136] tf32 bits

    const int tid = threadIdx.x;
    const int m0  = blockIdx.x * BM;
    const int nt  = blockIdx.y;           // edge-type block 0..6

    for (int i = tid; i < BM * 32; i += 256) {
        int r = i >> 5, c4 = i & 31;
        float4 v = make_float4(0.f, 0.f, 0.f, 0.f);
        if (m0 + r < nrows)
            v = *reinterpret_cast<const float4*>(&x[(size_t)(m0 + r) * C + c4 * 4]);
        uint32_t* dst = reinterpret_cast<uint32_t*>(&As[r * AS_STRIDE + c4 * 4]);
        dst[0] = tf32_rna(v.x); dst[1] = tf32_rna(v.y);
        dst[2] = tf32_rna(v.z); dst[3] = tf32_rna(v.w);
    }
    for (int i = tid; i < 128 * 32; i += 256) {
        int r = i >> 5, c4 = i & 31;
        float4 v = *reinterpret_cast<const float4*>(&w[(size_t)(nt * C + r) * C + c4 * 4]);
        uint32_t* dst = reinterpret_cast<uint32_t*>(&Bs[r * BS_STRIDE + c4 * 4]);
        dst[0] = tf32_rna(v.x); dst[1] = tf32_rna(v.y);
        dst[2] = tf32_rna(v.z); dst[3] = tf32_rna(v.w);
    }
    __syncthreads();

    const int wid = tid >> 5, lane = tid & 31;
    const int wm0 = (wid >> 1) * 64;
    const int wn0 = (wid & 1) * 64;
    const int gr = lane >> 2, gc = lane & 3;

    float acc[4][8][4];
#pragma unroll
    for (int f = 0; f < 4; ++f)
#pragma unroll
        for (int g = 0; g < 8; ++g)
#pragma unroll
            for (int q = 0; q < 4; ++q) acc[f][g][q] = 0.f;

    const uint32_t* Au = reinterpret_cast<const uint32_t*>(As);
    const uint32_t* Bu = reinterpret_cast<const uint32_t*>(Bs);

#pragma unroll
    for (int k0 = 0; k0 < 128; k0 += 8) {
        uint32_t a[4][4];
#pragma unroll
        for (int f = 0; f < 4; ++f) {
            const uint32_t* ap = &Au[(wm0 + 16 * f + gr) * AS_STRIDE + k0 + gc];
            a[f][0] = ap[0];
            a[f][1] = ap[8 * AS_STRIDE];
            a[f][2] = ap[4];
            a[f][3] = ap[8 * AS_STRIDE + 4];
        }
#pragma unroll
        for (int g = 0; g < 8; ++g) {
            const uint32_t* bp = &Bu[(k0 + gc) * BS_STRIDE + wn0 + 8 * g + gr];
            uint32_t b0 = bp[0];
            uint32_t b1 = bp[4 * BS_STRIDE];
#pragma unroll
            for (int f = 0; f < 4; ++f)
                mma_tf32(acc[f][g], a[f], b0, b1);
        }
    }

#pragma unroll
    for (int f = 0; f < 4; ++f) {
        int r0 = m0 + wm0 + 16 * f + gr;
#pragma unroll
        for (int g = 0; g < 8; ++g) {
            int colk = nt * C + wn0 + 8 * g + gc * 2;
            if (r0 < nrows)
                *reinterpret_cast<float2*>(&g_y[(size_t)r0 * KTOT + colk]) =
                    make_float2(acc[f][g][0], acc[f][g][1]);
            if (r0 + 8 < nrows)
                *reinterpret_cast<float2*>(&g_y[(size_t)(r0 + 8) * KTOT + colk]) =
                    make_float2(acc[f][g][2], acc[f][g][3]);
        }
    }
}

// K5: gather — one warp per row; out written once, no atomics
__global__ void gather_kernel(float* __restrict__ out, int nrows) {
    int wrp = (blockIdx.x * blockDim.x + threadIdx.x) >> 5;
    int lane = threadIdx.x & 31;
    if (wrp >= nrows) return;
    const float4* y4 = reinterpret_cast<const float4*>(g_y);
    // self slot (reference overwrites slot 6 with x; out contribution = x @ W6 = y block 6)
    float4 acc = y4[(size_t)wrp * (KTOT / 4) + (NET - 1) * 32 + lane];
    int base = wrp * NET;
#pragma unroll
    for (int t = 0; t < NET - 1; ++t) {
        unsigned beg = g_off[base + t], end = g_off[base + t + 1];
        if (end == beg) continue;
        float4 s = make_float4(0.f, 0.f, 0.f, 0.f);
        for (unsigned e = beg; e < end; ++e) {
            int c = g_elist[e];
            float4 v = y4[(size_t)c * (KTOT / 4) + t * 32 + lane];
            s.x += v.x; s.y += v.y; s.z += v.z; s.w += v.w;
        }
        float inv = 1.0f / (float)(end - beg);
        acc.x += s.x * inv; acc.y += s.y * inv;
        acc.z += s.z * inv; acc.w += s.w * inv;
    }
    reinterpret_cast<float4*>(out)[(size_t)wrp * 32 + lane] = acc;
}

// K6: column sums / sumsq
__global__ void stats_kernel(const float* __restrict__ out, int nrows) {
    int c = threadIdx.x;
    float s = 0.f, s2 = 0.f;
    for (int r = blockIdx.x; r < nrows; r += gridDim.x) {
        float v = out[(size_t)r * C + c];
        s += v; s2 += v * v;
    }
    atomicAdd(&g_stats[c], s);
    atomicAdd(&g_stats[C + c], s2);
}

// K6b: BN scale/shift
__global__ void bnfin_kernel(const float* __restrict__ gamma, const float* __restrict__ beta,
                             float inv_n) {
    int c = threadIdx.x;
    float mean = g_stats[c] * inv_n;
    float var  = g_stats[C + c] * inv_n - mean * mean;
    float sc   = gamma[c] * rsqrtf(var + 1e-5f);
    g_scale[c] = sc;
    g_shift[c] = beta[c] - mean * sc;
}

// K7: in-place normalize
__global__ void norm_kernel(float* __restrict__ out, size_t n4) {
    size_t i = (size_t)blockIdx.x * blockDim.x + threadIdx.x;
    size_t stride = (size_t)gridDim.x * blockDim.x;
    const float4* sc4 = reinterpret_cast<const float4*>(g_scale);
    const float4* sh4 = reinterpret_cast<const float4*>(g_shift);
    float4* o4 = reinterpret_cast<float4*>(out);
    for (size_t j = i; j < n4; j += stride) {
        int c4 = (int)(j & 31);
        float4 v = o4[j];
        float4 a = sc4[c4], b = sh4[c4];
        v.x = v.x * a.x + b.x;
        v.y = v.y * a.y + b.y;
        v.z = v.z * a.z + b.z;
        v.w = v.w * a.w + b.w;
        o4[j] = v;
    }
}

// ===================== launch ================================
extern "C" void kernel_launch(void* const* d_in, const int* in_sizes, int n_in,
                              void* d_out, int out_size) {
    const float* x     = (const float*)d_in[0];
    const int*   row   = (const int*)d_in[1];   // JAX default: int64 request -> int32 actual
    const int*   col   = (const int*)d_in[2];
    const int*   et    = (const int*)d_in[3];
    const float* w     = (const float*)d_in[4];
    const float* gamma = (const float*)d_in[5];
    const float* beta  = (const float*)d_in[6];
    float* out = (float*)d_out;

    int nrows = in_sizes[0] / C;          // 100000
    int E     = in_sizes[1];              // 700000
    int nseg  = nrows * NET;
    int nblk  = (nseg + 1023) / 1024;     // 684

    cudaFuncSetAttribute(gemm_kernel, cudaFuncAttributeMaxDynamicSharedMemorySize,
                         (int)GEMM_SMEM);

    zero_kernel<<<512, 256>>>(nseg);
    count_kernel<<<(E + 255) / 256, 256>>>(row, et, E);
    scan1_kernel<<<nblk, 1024>>>(nseg);
    scan2_kernel<<<1, 1024>>>(nblk, nseg);
    scan3_kernel<<<nblk, 1024>>>(nseg);
    fill_kernel<<<(E + 255) / 256, 256>>>(row, col, et, E);
    gemm_kernel<<<dim3((nrows + BM - 1) / BM, NET), 256, GEMM_SMEM>>>(x, w, nrows);
    gather_kernel<<<(nrows * 32 + 255) / 256, 256>>>(out, nrows);
    stats_kernel<<<1024, 128>>>(out, nrows);
    bnfin_kernel<<<1, 128>>>(gamma, beta, 1.0f / (float)nrows);
    norm_kernel<<<2048, 256>>>(out, (size_t)nrows * 32);
}